// round 8
// baseline (speedup 1.0000x reference)
#include <cuda_runtime.h>
#include <math.h>
#include <stdint.h>

#define N_LINES 1200
#define SAMP 5
#define PAD 8
#define NPROW (N_LINES*PAD)      // 9600
#define DIM 128
#define HH 128
#define WW 128
#define TOPK 10
#define CAND 48
#define GAPC 0.1f
#define NTILE 75                 // 9600/128
#define TILES_TOTAL (NTILE*NTILE)
#define NCTA 148
#define PITCH 136                // words per smem row (128 + 8 pad)

// ---------------- device scratch ----------------
__device__ float g_desc1t[HH*WW*DIM];
__device__ float g_desc2t[HH*WW*DIM];
__device__ float g_d1p[NPROW*DIM];      // k-permuted within 8-groups
__device__ float g_d2p[NPROW*DIM];
__device__ int   g_ns1[N_LINES];
__device__ int   g_ns2[N_LINES];
__device__ float g_ls [N_LINES*N_LINES];
__device__ float g_lsT[N_LINES*N_LINES];
__device__ int   g_candf[N_LINES*CAND];
__device__ int   g_candr[N_LINES*CAND];
__device__ int   g_topkf[N_LINES*TOPK];
__device__ int   g_topkr[N_LINES*TOPK];
__device__ float g_nwf[N_LINES*2*TOPK];
__device__ float g_nwr[N_LINES*2*TOPK];
__device__ int   g_mf[N_LINES];
__device__ int   g_mr[N_LINES];

// ---------------- PTX helpers (all baseline sm_80+) ----------------
__device__ __forceinline__ uint32_t smem_u32(const void* p) {
    uint32_t a;
    asm("{ .reg .u64 t; cvta.to.shared.u64 t, %1; cvt.u32.u64 %0, t; }" : "=r"(a) : "l"(p));
    return a;
}
#define CP_ASYNC16(dst, src) \
    asm volatile("cp.async.cg.shared.global [%0], [%1], 16;" :: "r"(dst), "l"(src) : "memory")
#define CP_COMMIT() asm volatile("cp.async.commit_group;" ::: "memory")
#define CP_WAIT0()  asm volatile("cp.async.wait_group 0;" ::: "memory")

__device__ __forceinline__ void mma_tf32(float* d, const uint32_t* a, const uint32_t* b) {
    asm volatile(
        "mma.sync.aligned.m16n8k8.row.col.f32.tf32.tf32.f32 "
        "{%0,%1,%2,%3}, {%4,%5,%6,%7}, {%8,%9}, {%0,%1,%2,%3};"
        : "+f"(d[0]), "+f"(d[1]), "+f"(d[2]), "+f"(d[3])
        : "r"(a[0]), "r"(a[1]), "r"(a[2]), "r"(a[3]), "r"(b[0]), "r"(b[1]));
}

// ---------------- transpose desc [d][y][x] -> [y][x][d] ----------------
__global__ void transpose_desc(const float* __restrict__ in, int which) {
    int idx = blockIdx.x * blockDim.x + threadIdx.x;
    if (idx >= HH*WW*DIM) return;
    int d = idx % DIM;
    int x = (idx / DIM) % WW;
    int y = idx / (DIM*WW);
    float v = in[d*(HH*WW) + y*WW + x];
    if (which == 0) g_desc1t[idx] = v; else g_desc2t[idx] = v;
}

// ---------------- sample + bilinear + normalize, k-permuted padded output ----------------
__global__ void sample_kernel(const float* __restrict__ seg, int which) {
    int pid  = blockIdx.x;            // 0..NPROW-1
    int line = pid >> 3;
    int k    = pid & 7;
    int d    = threadIdx.x;           // 0..127
    // permute k within 8-group: stored pos = (c&3)*2 + (c>>2)
    int c  = d & 7;
    int pd = (d & ~7) | ((c & 3) << 1) | (c >> 2);
    float* dout = (which == 0) ? g_d1p : g_d2p;

    if (k >= SAMP) { dout[pid*DIM + pd] = 0.0f; return; }

    float s0 = seg[line*4+0], s1 = seg[line*4+1];
    float e0 = seg[line*4+2], e1 = seg[line*4+3];
    float dy = __fsub_rn(e0, s0), dx = __fsub_rn(e1, s1);
    float len = __fsqrt_rn(__fadd_rn(__fmul_rn(dy,dy), __fmul_rn(dx,dx)));
    float nsf = floorf(__fmul_rn(len, 0.125f));
    nsf = fminf(fmaxf(nsf, 2.0f), 5.0f);
    float inv = __fsub_rn(nsf, 1.0f);
    float i0 = __fdiv_rn(dy, inv);
    float i1 = __fdiv_rn(dx, inv);
    float kf = (float)k;
    bool valid = kf < nsf;
    float p0 = valid ? __fadd_rn(s0, __fmul_rn(kf, i0)) : 0.0f;
    float p1 = valid ? __fadd_rn(s1, __fmul_rn(kf, i1)) : 0.0f;

    float xn = __fsub_rn(__fdiv_rn(__fmul_rn(2.0f, p1), 511.0f), 1.0f);
    float yn = __fsub_rn(__fdiv_rn(__fmul_rn(2.0f, p0), 511.0f), 1.0f);
    float ix = __fmul_rn(__fsub_rn(__fmul_rn(__fadd_rn(xn,1.0f),(float)WW),1.0f), 0.5f);
    float iy = __fmul_rn(__fsub_rn(__fmul_rn(__fadd_rn(yn,1.0f),(float)HH),1.0f), 0.5f);
    float x0f = floorf(ix), y0f = floorf(iy);
    float wx = __fsub_rn(ix, x0f), wy = __fsub_rn(iy, y0f);
    int x0 = (int)x0f, y0 = (int)y0f;

    const float* img = (which == 0) ? g_desc1t : g_desc2t;
    auto G = [&](int xi, int yi) -> float {
        bool inb = (xi >= 0) && (xi < WW) && (yi >= 0) && (yi < HH);
        int xc = min(max(xi, 0), WW-1);
        int yc = min(max(yi, 0), HH-1);
        float v = img[(yc*WW + xc)*DIM + d];
        return inb ? v : 0.0f;
    };
    float w00 = __fmul_rn(__fsub_rn(1.0f,wx), __fsub_rn(1.0f,wy));
    float w10 = __fmul_rn(wx, __fsub_rn(1.0f,wy));
    float w01 = __fmul_rn(__fsub_rn(1.0f,wx), wy);
    float w11 = __fmul_rn(wx, wy);
    float v = __fadd_rn(__fadd_rn(__fadd_rn(
                __fmul_rn(G(x0,y0),w00), __fmul_rn(G(x0+1,y0),w10)),
                __fmul_rn(G(x0,y0+1),w01)), __fmul_rn(G(x0+1,y0+1),w11));

    float t = __fmul_rn(v,v);
    #pragma unroll
    for (int o = 16; o; o >>= 1) t = __fadd_rn(t, __shfl_xor_sync(0xffffffffu, t, o));
    __shared__ float red[4];
    __shared__ float tot;
    if ((threadIdx.x & 31) == 0) red[threadIdx.x >> 5] = t;
    __syncthreads();
    if (threadIdx.x == 0)
        tot = __fsqrt_rn(__fadd_rn(__fadd_rn(red[0],red[1]),__fadd_rn(red[2],red[3])));
    __syncthreads();

    dout[pid*DIM + pd] = __fdiv_rn(v, tot);
    if (d == 0 && k == 0) {
        if (which == 0) g_ns1[line] = (int)nsf; else g_ns2[line] = (int)nsf;
    }
}

// ---------------- tensor-core linescore via mma.sync tf32 ----------------
#define SM_A 0
#define SM_B (128*PITCH)
#define SM_C (2*128*PITCH)
#define SM_TOTALW (3*128*PITCH)   // words

__device__ __forceinline__ void load_panel(uint32_t dstbase, const float* src) {
    const char* s = (const char*)src;
    int tid = threadIdx.x;
    #pragma unroll
    for (int i = 0; i < 16; i++) {
        int idx = tid + i*256;
        int row = idx >> 5, c16 = idx & 31;
        CP_ASYNC16(dstbase + (uint32_t)(row*PITCH + c16*4)*4, s + row*512 + c16*16);
    }
}

__global__ __launch_bounds__(256, 1) void linescore_tensor() {
    extern __shared__ __align__(16) float smem[];
    uint32_t sb = smem_u32(smem);
    float* A = smem;
    float* B = smem + SM_B;
    float* C = smem + SM_C;
    int tid = threadIdx.x;
    int wid = tid >> 5;
    int lane = tid & 31;
    int grp = lane >> 2;          // 0..7
    int tig = lane & 3;           // 0..3
    int wm = wid & 3;             // M quadrant (32 rows)
    int wn = wid >> 2;            // N half (64 cols)

    int cta = blockIdx.x;
    int t_start = (int)(((long long)cta     * TILES_TOTAL) / NCTA);
    int t_end   = (int)(((long long)(cta+1) * TILES_TOTAL) / NCTA);

    load_panel(sb + SM_A*4,  g_d1p + (t_start / NTILE) * 128 * DIM);
    load_panel(sb + SM_B*4,  g_d2p + (t_start % NTILE) * 128 * DIM);
    CP_COMMIT();

    for (int t = t_start; t < t_end; t++) {
        int it = t / NTILE, jt = t % NTILE;
        int nt = t + 1;
        bool havenext = nt < t_end;
        int nit = havenext ? nt / NTILE : -1;
        int njt = havenext ? nt % NTILE : 0;
        bool sameI = havenext && (nit == it);

        CP_WAIT0();
        __syncthreads();

        // ---- mma mainloop: warp computes 32x64 ----
        float acc[2][8][4];
        #pragma unroll
        for (int m = 0; m < 2; m++)
            #pragma unroll
            for (int n = 0; n < 8; n++)
                #pragma unroll
                for (int r = 0; r < 4; r++) acc[m][n][r] = 0.0f;

        int arow0 = wm*32 + grp;          // + m*16, +8 variants
        int bcol0 = wn*64 + grp;          // + n*8
        #pragma unroll
        for (int kk = 0; kk < 16; kk++) {
            int ko = kk*8 + 2*tig;
            uint32_t afr[2][4];
            #pragma unroll
            for (int m = 0; m < 2; m++) {
                float2 lo = *(const float2*)&A[(arow0 + m*16    )*PITCH + ko];
                float2 hi = *(const float2*)&A[(arow0 + m*16 + 8)*PITCH + ko];
                afr[m][0] = __float_as_uint(lo.x);   // row g,   k=tig
                afr[m][1] = __float_as_uint(hi.x);   // row g+8, k=tig
                afr[m][2] = __float_as_uint(lo.y);   // row g,   k=tig+4
                afr[m][3] = __float_as_uint(hi.y);   // row g+8, k=tig+4
            }
            uint32_t bfr[8][2];
            #pragma unroll
            for (int n = 0; n < 8; n++) {
                float2 bb = *(const float2*)&B[(bcol0 + n*8)*PITCH + ko];
                bfr[n][0] = __float_as_uint(bb.x);   // k=tig
                bfr[n][1] = __float_as_uint(bb.y);   // k=tig+4
            }
            #pragma unroll
            for (int m = 0; m < 2; m++)
                #pragma unroll
                for (int n = 0; n < 8; n++)
                    mma_tf32(acc[m][n], afr[m], bfr[n]);
        }
        __syncthreads();   // all warps done reading A/B

        // ---- stage C to smem ----
        #pragma unroll
        for (int m = 0; m < 2; m++) {
            int r0 = wm*32 + m*16 + grp;
            #pragma unroll
            for (int n = 0; n < 8; n++) {
                int cb = wn*64 + n*8 + 2*tig;
                *(float2*)&C[r0*PITCH + cb]     = make_float2(acc[m][n][0], acc[m][n][1]);
                *(float2*)&C[(r0+8)*PITCH + cb] = make_float2(acc[m][n][2], acc[m][n][3]);
            }
        }

        // prefetch next panels (B dead; A dead too after sync above)
        if (havenext) {
            if (!sameI) load_panel(sb + SM_A*4, g_d1p + nit*128*DIM);
            load_panel(sb + SM_B*4, g_d2p + njt*128*DIM);
            CP_COMMIT();
        }
        __syncthreads();   // C visible

        // ---- epilogue: one thread per line pair (validated 5x5 logic) ----
        {
            int iL = tid >> 4, jL = tid & 15;
            int iglob = it*16 + iL, jglob = jt*16 + jL;
            int na = g_ns1[iglob], nb = g_ns2[jglob];
            float sc[5][5];
            #pragma unroll
            for (int s = 0; s < 5; s++) {
                const float* row = &C[(iL*8 + s)*PITCH + jL*8];
                float4 v4 = *(const float4*)row;
                float  v5 = row[4];
                float dv[5] = {v4.x, v4.y, v4.z, v4.w, v5};
                #pragma unroll
                for (int u = 0; u < 5; u++)
                    sc[s][u] = (s < na && u < nb) ? dv[u] : -1.0f;
            }
            float sum1 = 0.0f, c1 = 0.0f;
            #pragma unroll
            for (int s = 0; s < 5; s++) {
                float m = sc[s][0];
                #pragma unroll
                for (int u = 1; u < 5; u++) m = fmaxf(m, sc[s][u]);
                if (m != -1.0f) { sum1 += m; c1 += 1.0f; }
            }
            float sum2 = 0.0f, c2 = 0.0f;
            #pragma unroll
            for (int u = 0; u < 5; u++) {
                float m = sc[0][u];
                #pragma unroll
                for (int s = 1; s < 5; s++) m = fmaxf(m, sc[s][u]);
                if (m != -1.0f) { sum2 += m; c2 += 1.0f; }
            }
            float ls = (sum1/c1 + sum2/c2) * 0.5f;
            g_ls [iglob*N_LINES + jglob] = ls;
            g_lsT[jglob*N_LINES + iglob] = ls;
        }
        __syncthreads();   // epilogue done before next tile overwrites C
    }
}

// ---------------- top-CAND candidate selection (tf32 scores) ----------------
__global__ void cand_kernel() {
    int row = blockIdx.x;
    int rev = blockIdx.y;
    int tid = threadIdx.x;
    int lane = tid & 31, warp = tid >> 5;
    __shared__ float vals[N_LINES];
    __shared__ float wv[8];
    __shared__ int   wi[8];

    const float* src = rev ? (g_lsT + row*N_LINES) : (g_ls + row*N_LINES);
    for (int j = tid; j < N_LINES; j += 256) vals[j] = src[j];
    __syncthreads();

    int* cand = rev ? g_candr : g_candf;
    for (int p = 0; p < CAND; p++) {
        float best = -1e30f; int bidx = -1;
        for (int j = tid; j < N_LINES; j += 256) {
            float v = vals[j];
            if (v > best || (v == best && j > bidx)) { best = v; bidx = j; }
        }
        #pragma unroll
        for (int o = 16; o; o >>= 1) {
            float ov = __shfl_xor_sync(0xffffffffu, best, o);
            int   oi = __shfl_xor_sync(0xffffffffu, bidx, o);
            if (ov > best || (ov == best && oi > bidx)) { best = ov; bidx = oi; }
        }
        if (lane == 0) { wv[warp] = best; wi[warp] = bidx; }
        __syncthreads();
        if (warp == 0) {
            best = (lane < 8) ? wv[lane] : -1e30f;
            bidx = (lane < 8) ? wi[lane] : -1;
            #pragma unroll
            for (int o = 4; o; o >>= 1) {
                float ov = __shfl_xor_sync(0xffffffffu, best, o);
                int   oi = __shfl_xor_sync(0xffffffffu, bidx, o);
                if (ov > best || (ov == best && oi > bidx)) { best = ov; bidx = oi; }
            }
            if (lane == 0) {
                cand[row*CAND + p] = bidx;
                vals[bidx] = -1e30f;
            }
        }
        __syncthreads();
    }
}

// ---------------- exact refinement with compensated dots ----------------
__global__ __launch_bounds__(256) void refine_kernel() {
    int r = blockIdx.x;
    int rev = blockIdx.y;
    int tid = threadIdx.x;
    __shared__ float F[5][DIM];
    __shared__ double dm[CAND][5][5];
    __shared__ double scs[CAND];
    __shared__ int cnd[CAND];

    if (tid < CAND) cnd[tid] = rev ? g_candr[r*CAND+tid] : g_candf[r*CAND+tid];
    const float* Ffix = rev ? (g_d2p + r*PAD*DIM) : (g_d1p + r*PAD*DIM);
    for (int idx = tid; idx < SAMP*DIM; idx += 256)
        F[idx/DIM][idx%DIM] = Ffix[idx];
    __syncthreads();

    if (tid < CAND*SAMP) {
        int c = tid / SAMP, v = tid % SAMP;
        int j = cnd[c];
        const float* Vg = rev ? (g_d1p + (j*PAD+v)*DIM) : (g_d2p + (j*PAD+v)*DIM);
        float s[5], comp[5];
        #pragma unroll
        for (int f = 0; f < 5; f++) { s[f] = 0.0f; comp[f] = 0.0f; }
        for (int k = 0; k < DIM; k++) {
            float b = Vg[k];
            #pragma unroll
            for (int f = 0; f < 5; f++) {
                float a = F[f][k];
                float p  = __fmul_rn(a, b);
                float ep = __fmaf_rn(a, b, -p);
                float t  = __fadd_rn(s[f], p);
                float z  = __fsub_rn(t, s[f]);
                float e  = __fadd_rn(__fsub_rn(s[f], __fsub_rn(t, z)),
                                     __fsub_rn(p, z));
                s[f] = t;
                comp[f] = __fadd_rn(comp[f], __fadd_rn(ep, e));
            }
        }
        #pragma unroll
        for (int f = 0; f < 5; f++) {
            double d = (double)s[f] + (double)comp[f];
            if (!rev) dm[c][f][v] = d;
            else      dm[c][v][f] = d;
        }
    }
    __syncthreads();

    if (tid < CAND) {
        int c = tid; int j = cnd[c];
        int na = rev ? g_ns1[j] : g_ns1[r];
        int nb = rev ? g_ns2[r] : g_ns2[j];
        double sum1 = 0.0, cc1 = 0.0, sum2 = 0.0, cc2 = 0.0;
        for (int a = 0; a < 5; a++) {
            double m = -1.0;
            for (int b = 0; b < 5; b++) {
                double val = (a < na && b < nb) ? dm[c][a][b] : -1.0;
                if (val > m) m = val;
            }
            if (a < na) { sum1 += m; cc1 += 1.0; }
        }
        for (int b = 0; b < 5; b++) {
            double m = -1.0;
            for (int a = 0; a < 5; a++) {
                double val = (a < na && b < nb) ? dm[c][a][b] : -1.0;
                if (val > m) m = val;
            }
            if (b < nb) { sum2 += m; cc2 += 1.0; }
        }
        scs[c] = (sum1/cc1 + sum2/cc2) * 0.5;
    }
    __syncthreads();

    if (tid == 0) {
        bool used[CAND];
        #pragma unroll
        for (int c = 0; c < CAND; c++) used[c] = false;
        int* out = rev ? &g_topkr[r*TOPK] : &g_topkf[r*TOPK];
        for (int p = 0; p < TOPK; p++) {
            double best = -1e300; int bidx = -1, bc = -1;
            for (int c = 0; c < CAND; c++) {
                if (used[c]) continue;
                double v = scs[c]; int idx = cnd[c];
                if (v > best || (v == best && idx > bidx)) { best = v; bidx = idx; bc = c; }
            }
            used[bc] = true;
            out[TOPK-1-p] = bidx;
        }
    }
}

// ---------------- Needleman-Wunsch ----------------
__device__ __forceinline__ float nw5(const float sc[5][5]) {
    float prev[6] = {0,0,0,0,0,0};
    #pragma unroll
    for (int r = 0; r < 5; r++) {
        float nr[6];
        nr[0] = 0.0f;
        float left = 0.0f;
        #pragma unroll
        for (int c = 0; c < 5; c++) {
            float cur = fmaxf(fmaxf(left, prev[c+1]), prev[c] + (sc[r][c] - GAPC));
            nr[c+1] = cur; left = cur;
        }
        #pragma unroll
        for (int c = 0; c < 6; c++) prev[c] = nr[c];
    }
    return prev[5];
}

__device__ __forceinline__ void dot_block(int i, int j, int na, int nb, float dm[5][5]) {
    const float4* pa = (const float4*)(g_d1p + i*PAD*DIM);
    const float4* pb = (const float4*)(g_d2p + j*PAD*DIM);
    float acc[5][5];
    #pragma unroll
    for (int a = 0; a < 5; a++)
        #pragma unroll
        for (int b = 0; b < 5; b++) acc[a][b] = 0.0f;
    for (int kk = 0; kk < DIM/4; kk++) {
        float4 x[5], y[5];
        #pragma unroll
        for (int a = 0; a < 5; a++) x[a] = pa[a*(DIM/4) + kk];
        #pragma unroll
        for (int b = 0; b < 5; b++) y[b] = pb[b*(DIM/4) + kk];
        #pragma unroll
        for (int a = 0; a < 5; a++)
            #pragma unroll
            for (int b = 0; b < 5; b++)
                acc[a][b] += x[a].x*y[b].x + x[a].y*y[b].y + x[a].z*y[b].z + x[a].w*y[b].w;
    }
    #pragma unroll
    for (int a = 0; a < 5; a++)
        #pragma unroll
        for (int b = 0; b < 5; b++)
            dm[a][b] = (a < na && b < nb) ? acc[a][b] : -1.0f;
}

__global__ void nw_fwd_kernel() {
    int id = blockIdx.x * blockDim.x + threadIdx.x;
    if (id >= N_LINES*2*TOPK) return;
    int i = id / (2*TOPK);
    int t = id % (2*TOPK);
    int j = g_topkf[i*TOPK + (t % TOPK)];
    float dm[5][5];
    dot_block(i, j, g_ns1[i], g_ns2[j], dm);
    if (t >= TOPK) {
        #pragma unroll
        for (int a = 0; a < 5; a++) {
            float tmp = dm[a][0]; dm[a][0] = dm[a][4]; dm[a][4] = tmp;
            tmp = dm[a][1]; dm[a][1] = dm[a][3]; dm[a][3] = tmp;
        }
    }
    g_nwf[id] = nw5(dm);
}

__global__ void nw_rev_kernel() {
    int id = blockIdx.x * blockDim.x + threadIdx.x;
    if (id >= N_LINES*2*TOPK) return;
    int j = id / (2*TOPK);
    int u = id % (2*TOPK);
    int i = g_topkr[j*TOPK + (u % TOPK)];
    float dm[5][5];
    dot_block(i, j, g_ns1[i], g_ns2[j], dm);
    float sc[5][5];
    #pragma unroll
    for (int b = 0; b < 5; b++)
        #pragma unroll
        for (int a = 0; a < 5; a++) sc[b][a] = dm[a][b];
    if (u >= TOPK) {
        #pragma unroll
        for (int b = 0; b < 5; b++) {
            float tmp = sc[b][0]; sc[b][0] = sc[b][4]; sc[b][4] = tmp;
            tmp = sc[b][1]; sc[b][1] = sc[b][3]; sc[b][3] = tmp;
        }
    }
    g_nwr[j*2*TOPK + u] = nw5(sc);
}

__global__ void match_kernel() {
    int gi = blockIdx.x * blockDim.x + threadIdx.x;
    if (gi >= 2*N_LINES) return;
    int rev = gi >= N_LINES;
    int i = rev ? (gi - N_LINES) : gi;
    const float* nw = rev ? g_nwr : g_nwf;
    const int* topk = rev ? g_topkr : g_topkf;
    float best = nw[i*2*TOPK];
    int bt = 0;
    #pragma unroll
    for (int t = 1; t < 2*TOPK; t++) {
        float v = nw[i*2*TOPK + t];
        if (v > best) { best = v; bt = t; }
    }
    int m = topk[i*TOPK + (bt % TOPK)];
    if (rev) g_mr[i] = m; else g_mf[i] = m;
}

__global__ void finalize_kernel(void* out, int out_size) {
    int idx = blockIdx.x * blockDim.x + threadIdx.x;
    if (out_size >= N_LINES + N_LINES*2*TOPK) {
        float* o = (float*)out;
        if (idx < N_LINES) {
            int mf = g_mf[idx];
            o[idx] = (g_mr[mf] == idx) ? (float)mf : -1.0f;
        } else if (idx < N_LINES + N_LINES*2*TOPK) {
            o[idx] = g_nwf[idx - N_LINES];
        }
    } else if (out_size == N_LINES) {
        if (idx < N_LINES) {
            int mf = g_mf[idx];
            ((int*)out)[idx] = (g_mr[mf] == idx) ? mf : -1;
        }
    } else if (out_size == N_LINES*2*TOPK) {
        if (idx < N_LINES*2*TOPK) ((float*)out)[idx] = g_nwf[idx];
    }
}

// ---------------- launch ----------------
extern "C" void kernel_launch(void* const* d_in, const int* in_sizes, int n_in,
                              void* d_out, int out_size) {
    const float* seg1  = (const float*)d_in[0];
    const float* seg2  = (const float*)d_in[1];
    const float* desc1 = (const float*)d_in[2];
    const float* desc2 = (const float*)d_in[3];

    static int smem_set = 0;
    if (!smem_set) {
        cudaFuncSetAttribute(linescore_tensor,
                             cudaFuncAttributeMaxDynamicSharedMemorySize,
                             SM_TOTALW * 4);
        smem_set = 1;
    }

    int tr_blocks = (HH*WW*DIM + 255) / 256;
    transpose_desc<<<tr_blocks, 256>>>(desc1, 0);
    transpose_desc<<<tr_blocks, 256>>>(desc2, 1);

    sample_kernel<<<NPROW, DIM>>>(seg1, 0);
    sample_kernel<<<NPROW, DIM>>>(seg2, 1);

    linescore_tensor<<<NCTA, 256, SM_TOTALW * 4>>>();

    dim3 cg(N_LINES, 2);
    cand_kernel<<<cg, 256>>>();
    refine_kernel<<<cg, 256>>>();

    int nw_total = N_LINES*2*TOPK;
    nw_fwd_kernel<<<(nw_total + 127)/128, 128>>>();
    nw_rev_kernel<<<(nw_total + 127)/128, 128>>>();

    match_kernel<<<(2*N_LINES + 127)/128, 128>>>();

    int out_threads = N_LINES + N_LINES*2*TOPK;
    finalize_kernel<<<(out_threads + 255)/256, 256>>>(d_out, out_size);
}

// round 9
// speedup vs baseline: 1.4331x; 1.4331x over previous
#include <cuda_runtime.h>
#include <math.h>
#include <stdint.h>

#define N_LINES 1200
#define SAMP 5
#define NPTS (N_LINES*SAMP)     // 6000
#define DIM 128
#define HH 128
#define WW 128
#define TOPK 10
#define CAND 16
#define GAPC 0.1f
#define BT 16                    // lines per block edge
#define KC 32                    // K chunk
#define ASTR 164                 // A smem row: 16 lines x 10 floats (dup pairs) + 4 pad
#define BSTR 132                 // B smem row: 16 lines x 8 floats (b4 dup) + 4 pad

typedef unsigned long long ull;

// ---------------- device scratch ----------------
__device__ float g_desc1t[HH*WW*DIM];   // [y][x][d]
__device__ float g_desc2t[HH*WW*DIM];
__device__ float g_d1[NPTS*DIM];        // sampled normalized descriptors [pt][d]
__device__ float g_d2[NPTS*DIM];
__device__ int   g_ns1[N_LINES];
__device__ int   g_ns2[N_LINES];
__device__ float g_ls [N_LINES*N_LINES];
__device__ float g_lsT[N_LINES*N_LINES];
__device__ int   g_candf[N_LINES*CAND];
__device__ int   g_candr[N_LINES*CAND];
__device__ int   g_topkf[N_LINES*TOPK];
__device__ int   g_topkr[N_LINES*TOPK];
__device__ float g_nwf[N_LINES*2*TOPK];
__device__ float g_nwr[N_LINES*2*TOPK];
__device__ int   g_mf[N_LINES];
__device__ int   g_mr[N_LINES];

// packed f32x2 FMA: per-lane IEEE fma, bit-identical to scalar FFMA chains
__device__ __forceinline__ void fma2(ull& acc, ull a, ull b) {
    asm("fma.rn.f32x2 %0, %1, %2, %0;" : "+l"(acc) : "l"(a), "l"(b));
}
__device__ __forceinline__ float2 unpack2(ull v) {
    uint32_t lo, hi;
    asm("mov.b64 {%0, %1}, %2;" : "=r"(lo), "=r"(hi) : "l"(v));
    return make_float2(__uint_as_float(lo), __uint_as_float(hi));
}

// ---------------- transpose desc [d][y][x] -> [y][x][d] ----------------
__global__ void transpose_desc(const float* __restrict__ in, int which) {
    int idx = blockIdx.x * blockDim.x + threadIdx.x;
    if (idx >= HH*WW*DIM) return;
    int d = idx % DIM;
    int x = (idx / DIM) % WW;
    int y = idx / (DIM*WW);
    float v = in[d*(HH*WW) + y*WW + x];
    if (which == 0) g_desc1t[idx] = v; else g_desc2t[idx] = v;
}

// ---------------- sample points + bilinear descriptors + normalize ----------------
__global__ void sample_kernel(const float* __restrict__ seg, int which) {
    int pid  = blockIdx.x;            // 0..NPTS-1
    int line = pid / SAMP;
    int k    = pid % SAMP;
    int d    = threadIdx.x;           // 0..127

    float s0 = seg[line*4+0], s1 = seg[line*4+1];
    float e0 = seg[line*4+2], e1 = seg[line*4+3];
    float dy = __fsub_rn(e0, s0), dx = __fsub_rn(e1, s1);
    float len = __fsqrt_rn(__fadd_rn(__fmul_rn(dy,dy), __fmul_rn(dx,dx)));
    float nsf = floorf(__fmul_rn(len, 0.125f));
    nsf = fminf(fmaxf(nsf, 2.0f), 5.0f);
    float inv = __fsub_rn(nsf, 1.0f);
    float i0 = __fdiv_rn(dy, inv);
    float i1 = __fdiv_rn(dx, inv);
    float kf = (float)k;
    bool valid = kf < nsf;
    float p0 = valid ? __fadd_rn(s0, __fmul_rn(kf, i0)) : 0.0f;
    float p1 = valid ? __fadd_rn(s1, __fmul_rn(kf, i1)) : 0.0f;

    float xn = __fsub_rn(__fdiv_rn(__fmul_rn(2.0f, p1), 511.0f), 1.0f);
    float yn = __fsub_rn(__fdiv_rn(__fmul_rn(2.0f, p0), 511.0f), 1.0f);
    float ix = __fmul_rn(__fsub_rn(__fmul_rn(__fadd_rn(xn,1.0f),(float)WW),1.0f), 0.5f);
    float iy = __fmul_rn(__fsub_rn(__fmul_rn(__fadd_rn(yn,1.0f),(float)HH),1.0f), 0.5f);
    float x0f = floorf(ix), y0f = floorf(iy);
    float wx = __fsub_rn(ix, x0f), wy = __fsub_rn(iy, y0f);
    int x0 = (int)x0f, y0 = (int)y0f;

    const float* img = (which == 0) ? g_desc1t : g_desc2t;
    auto G = [&](int xi, int yi) -> float {
        bool inb = (xi >= 0) && (xi < WW) && (yi >= 0) && (yi < HH);
        int xc = min(max(xi, 0), WW-1);
        int yc = min(max(yi, 0), HH-1);
        float v = img[(yc*WW + xc)*DIM + d];
        return inb ? v : 0.0f;
    };
    float w00 = __fmul_rn(__fsub_rn(1.0f,wx), __fsub_rn(1.0f,wy));
    float w10 = __fmul_rn(wx, __fsub_rn(1.0f,wy));
    float w01 = __fmul_rn(__fsub_rn(1.0f,wx), wy);
    float w11 = __fmul_rn(wx, wy);
    float v = __fadd_rn(__fadd_rn(__fadd_rn(
                __fmul_rn(G(x0,y0),w00), __fmul_rn(G(x0+1,y0),w10)),
                __fmul_rn(G(x0,y0+1),w01)), __fmul_rn(G(x0+1,y0+1),w11));

    float t = __fmul_rn(v,v);
    #pragma unroll
    for (int o = 16; o; o >>= 1) t = __fadd_rn(t, __shfl_xor_sync(0xffffffffu, t, o));
    __shared__ float red[4];
    __shared__ float tot;
    if ((threadIdx.x & 31) == 0) red[threadIdx.x >> 5] = t;
    __syncthreads();
    if (threadIdx.x == 0)
        tot = __fsqrt_rn(__fadd_rn(__fadd_rn(red[0],red[1]),__fadd_rn(red[2],red[3])));
    __syncthreads();

    float* dout = (which == 0) ? g_d1 : g_d2;
    dout[pid*DIM + d] = __fdiv_rn(v, tot);

    if (d == 0 && k == 0) {
        if (which == 0) g_ns1[line] = (int)nsf; else g_ns2[line] = (int)nsf;
    }
}

// ---------------- fused GEMM + line-score reduction (packed f32x2 FMA) ----------------
// A smem: duplicated pairs (a,a) per sample -> direct LDS.64 operands for fma2
// B smem: 8-slot groups (b0..b4, b4, pad, pad) -> (b0,b1),(b2,b3),(b4,b4) LDS.64
__global__ __launch_bounds__(256) void linescore_kernel() {
    __shared__ __align__(16) float As[KC][ASTR];
    __shared__ __align__(16) float Bs[KC][BSTR];
    int tid = threadIdx.x;
    int ti = tid >> 4;        // 0..15
    int tj = tid & 15;        // 0..15
    int ib = blockIdx.y * BT;
    int jb = blockIdx.x * BT;

    const float* Ag = g_d1 + (ib*SAMP)*DIM;
    const float* Bg = g_d2 + (jb*SAMP)*DIM;

    ull acc[5][3];
    #pragma unroll
    for (int s = 0; s < 5; s++)
        #pragma unroll
        for (int p = 0; p < 3; p++) acc[s][p] = 0ull;

    for (int k0 = 0; k0 < DIM; k0 += KC) {
        // load 80 rows x KC floats of each operand (float4), store transposed
        for (int idx = tid; idx < 80*(KC/4); idx += 256) {
            int row = idx >> 3;
            int c   = idx & 7;
            int l = row / 5, s = row % 5;
            float4 va = *(const float4*)(Ag + row*DIM + k0 + c*4);
            float av[4] = {va.x, va.y, va.z, va.w};
            #pragma unroll
            for (int q = 0; q < 4; q++) {
                int kq = c*4 + q;
                As[kq][l*10 + s*2    ] = av[q];
                As[kq][l*10 + s*2 + 1] = av[q];
            }
            float4 vb = *(const float4*)(Bg + row*DIM + k0 + c*4);
            float bv[4] = {vb.x, vb.y, vb.z, vb.w};
            #pragma unroll
            for (int q = 0; q < 4; q++) {
                int kq = c*4 + q;
                Bs[kq][l*8 + s] = bv[q];
                if (s == 4) Bs[kq][l*8 + 5] = bv[q];
            }
        }
        __syncthreads();
        #pragma unroll
        for (int k = 0; k < KC; k++) {
            ull a[5];
            #pragma unroll
            for (int s = 0; s < 5; s++)
                a[s] = *(const ull*)&As[k][ti*10 + s*2];
            ull b01 = *(const ull*)&Bs[k][tj*8    ];
            ull b23 = *(const ull*)&Bs[k][tj*8 + 2];
            ull b44 = *(const ull*)&Bs[k][tj*8 + 4];
            #pragma unroll
            for (int s = 0; s < 5; s++) {
                fma2(acc[s][0], a[s], b01);
                fma2(acc[s][1], a[s], b23);
                fma2(acc[s][2], a[s], b44);
            }
        }
        __syncthreads();
    }

    int i = ib + ti, j = jb + tj;
    int na = g_ns1[i], nb = g_ns2[j];

    float sc[5][5];
    #pragma unroll
    for (int s = 0; s < 5; s++) {
        float2 p0 = unpack2(acc[s][0]);
        float2 p1 = unpack2(acc[s][1]);
        float2 p2 = unpack2(acc[s][2]);
        float dv[5] = {p0.x, p0.y, p1.x, p1.y, p2.x};
        #pragma unroll
        for (int u = 0; u < 5; u++)
            sc[s][u] = (s < na && u < nb) ? dv[u] : -1.0f;
    }

    float sum1 = 0.0f, c1 = 0.0f;
    #pragma unroll
    for (int s = 0; s < 5; s++) {
        float m = sc[s][0];
        #pragma unroll
        for (int u = 1; u < 5; u++) m = fmaxf(m, sc[s][u]);
        if (m != -1.0f) { sum1 += m; c1 += 1.0f; }
    }
    float sum2 = 0.0f, c2 = 0.0f;
    #pragma unroll
    for (int u = 0; u < 5; u++) {
        float m = sc[0][u];
        #pragma unroll
        for (int s = 1; s < 5; s++) m = fmaxf(m, sc[s][u]);
        if (m != -1.0f) { sum2 += m; c2 += 1.0f; }
    }
    float ls = (sum1/c1 + sum2/c2) * 0.5f;
    g_ls [i*N_LINES + j] = ls;
    g_lsT[j*N_LINES + i] = ls;
}

// ---------------- top-CAND candidate selection ----------------
__global__ void cand_kernel() {
    int row = blockIdx.x;
    int rev = blockIdx.y;
    int tid = threadIdx.x;
    int lane = tid & 31, warp = tid >> 5;
    __shared__ float vals[N_LINES];
    __shared__ float wv[8];
    __shared__ int   wi[8];

    const float* src = rev ? (g_lsT + row*N_LINES) : (g_ls + row*N_LINES);
    for (int j = tid; j < N_LINES; j += 256) vals[j] = src[j];
    __syncthreads();

    int* cand = rev ? g_candr : g_candf;
    for (int p = 0; p < CAND; p++) {
        float best = -1e30f; int bidx = -1;
        for (int j = tid; j < N_LINES; j += 256) {
            float v = vals[j];
            if (v > best || (v == best && j > bidx)) { best = v; bidx = j; }
        }
        #pragma unroll
        for (int o = 16; o; o >>= 1) {
            float ov = __shfl_xor_sync(0xffffffffu, best, o);
            int   oi = __shfl_xor_sync(0xffffffffu, bidx, o);
            if (ov > best || (ov == best && oi > bidx)) { best = ov; bidx = oi; }
        }
        if (lane == 0) { wv[warp] = best; wi[warp] = bidx; }
        __syncthreads();
        if (warp == 0) {
            best = (lane < 8) ? wv[lane] : -1e30f;
            bidx = (lane < 8) ? wi[lane] : -1;
            #pragma unroll
            for (int o = 4; o; o >>= 1) {
                float ov = __shfl_xor_sync(0xffffffffu, best, o);
                int   oi = __shfl_xor_sync(0xffffffffu, bidx, o);
                if (ov > best || (ov == best && oi > bidx)) { best = ov; bidx = oi; }
            }
            if (lane == 0) {
                cand[row*CAND + p] = bidx;
                vals[bidx] = -1e30f;
            }
        }
        __syncthreads();
    }
}

// ---------------- exact refinement with compensated dots ----------------
__global__ __launch_bounds__(128) void refine_kernel() {
    int r = blockIdx.x;
    int rev = blockIdx.y;
    int tid = threadIdx.x;
    __shared__ float F[5][DIM];
    __shared__ double dm[CAND][5][5];
    __shared__ double scs[CAND];
    __shared__ int cnd[CAND];

    if (tid < CAND) cnd[tid] = rev ? g_candr[r*CAND+tid] : g_candf[r*CAND+tid];
    const float* Ffix = rev ? (g_d2 + r*SAMP*DIM) : (g_d1 + r*SAMP*DIM);
    for (int idx = tid; idx < SAMP*DIM; idx += 128)
        F[idx/DIM][idx%DIM] = Ffix[idx];
    __syncthreads();

    if (tid < CAND*SAMP) {
        int c = tid / SAMP, v = tid % SAMP;
        int j = cnd[c];
        const float* Vg = rev ? (g_d1 + (j*SAMP+v)*DIM) : (g_d2 + (j*SAMP+v)*DIM);
        float s[5], comp[5];
        #pragma unroll
        for (int f = 0; f < 5; f++) { s[f] = 0.0f; comp[f] = 0.0f; }
        for (int k = 0; k < DIM; k++) {
            float b = Vg[k];
            #pragma unroll
            for (int f = 0; f < 5; f++) {
                float a = F[f][k];
                float p  = __fmul_rn(a, b);
                float ep = __fmaf_rn(a, b, -p);
                float t  = __fadd_rn(s[f], p);
                float z  = __fsub_rn(t, s[f]);
                float e  = __fadd_rn(__fsub_rn(s[f], __fsub_rn(t, z)),
                                     __fsub_rn(p, z));
                s[f] = t;
                comp[f] = __fadd_rn(comp[f], __fadd_rn(ep, e));
            }
        }
        #pragma unroll
        for (int f = 0; f < 5; f++) {
            double d = (double)s[f] + (double)comp[f];
            if (!rev) dm[c][f][v] = d;
            else      dm[c][v][f] = d;
        }
    }
    __syncthreads();

    if (tid < CAND) {
        int c = tid; int j = cnd[c];
        int na = rev ? g_ns1[j] : g_ns1[r];
        int nb = rev ? g_ns2[r] : g_ns2[j];
        double sum1 = 0.0, cc1 = 0.0, sum2 = 0.0, cc2 = 0.0;
        for (int a = 0; a < 5; a++) {
            double m = -1.0;
            for (int b = 0; b < 5; b++) {
                double val = (a < na && b < nb) ? dm[c][a][b] : -1.0;
                if (val > m) m = val;
            }
            if (a < na) { sum1 += m; cc1 += 1.0; }
        }
        for (int b = 0; b < 5; b++) {
            double m = -1.0;
            for (int a = 0; a < 5; a++) {
                double val = (a < na && b < nb) ? dm[c][a][b] : -1.0;
                if (val > m) m = val;
            }
            if (b < nb) { sum2 += m; cc2 += 1.0; }
        }
        scs[c] = (sum1/cc1 + sum2/cc2) * 0.5;
    }
    __syncthreads();

    if (tid == 0) {
        bool used[CAND];
        #pragma unroll
        for (int c = 0; c < CAND; c++) used[c] = false;
        int* out = rev ? &g_topkr[r*TOPK] : &g_topkf[r*TOPK];
        for (int p = 0; p < TOPK; p++) {
            double best = -1e300; int bidx = -1, bc = -1;
            for (int c = 0; c < CAND; c++) {
                if (used[c]) continue;
                double v = scs[c]; int idx = cnd[c];
                if (v > best || (v == best && idx > bidx)) { best = v; bidx = idx; bc = c; }
            }
            used[bc] = true;
            out[TOPK-1-p] = bidx;
        }
    }
}

// ---------------- Needleman-Wunsch ----------------
__device__ __forceinline__ float nw5(const float sc[5][5]) {
    float prev[6] = {0,0,0,0,0,0};
    #pragma unroll
    for (int r = 0; r < 5; r++) {
        float nr[6];
        nr[0] = 0.0f;
        float left = 0.0f;
        #pragma unroll
        for (int c = 0; c < 5; c++) {
            float cur = fmaxf(fmaxf(left, prev[c+1]), prev[c] + (sc[r][c] - GAPC));
            nr[c+1] = cur; left = cur;
        }
        #pragma unroll
        for (int c = 0; c < 6; c++) prev[c] = nr[c];
    }
    return prev[5];
}

__device__ __forceinline__ void dot_block(int i, int j, int na, int nb, float dm[5][5]) {
    const float4* pa = (const float4*)(g_d1 + i*SAMP*DIM);
    const float4* pb = (const float4*)(g_d2 + j*SAMP*DIM);
    float acc[5][5];
    #pragma unroll
    for (int a = 0; a < 5; a++)
        #pragma unroll
        for (int b = 0; b < 5; b++) acc[a][b] = 0.0f;
    for (int kk = 0; kk < DIM/4; kk++) {
        float4 x[5], y[5];
        #pragma unroll
        for (int a = 0; a < 5; a++) x[a] = pa[a*(DIM/4) + kk];
        #pragma unroll
        for (int b = 0; b < 5; b++) y[b] = pb[b*(DIM/4) + kk];
        #pragma unroll
        for (int a = 0; a < 5; a++)
            #pragma unroll
            for (int b = 0; b < 5; b++)
                acc[a][b] += x[a].x*y[b].x + x[a].y*y[b].y + x[a].z*y[b].z + x[a].w*y[b].w;
    }
    #pragma unroll
    for (int a = 0; a < 5; a++)
        #pragma unroll
        for (int b = 0; b < 5; b++)
            dm[a][b] = (a < na && b < nb) ? acc[a][b] : -1.0f;
}

__global__ void nw_fwd_kernel() {
    int id = blockIdx.x * blockDim.x + threadIdx.x;
    if (id >= N_LINES*2*TOPK) return;
    int i = id / (2*TOPK);
    int t = id % (2*TOPK);
    int j = g_topkf[i*TOPK + (t % TOPK)];
    float dm[5][5];
    dot_block(i, j, g_ns1[i], g_ns2[j], dm);
    if (t >= TOPK) {
        #pragma unroll
        for (int a = 0; a < 5; a++) {
            float tmp = dm[a][0]; dm[a][0] = dm[a][4]; dm[a][4] = tmp;
            tmp = dm[a][1]; dm[a][1] = dm[a][3]; dm[a][3] = tmp;
        }
    }
    g_nwf[id] = nw5(dm);
}

__global__ void nw_rev_kernel() {
    int id = blockIdx.x * blockDim.x + threadIdx.x;
    if (id >= N_LINES*2*TOPK) return;
    int j = id / (2*TOPK);
    int u = id % (2*TOPK);
    int i = g_topkr[j*TOPK + (u % TOPK)];
    float dm[5][5];
    dot_block(i, j, g_ns1[i], g_ns2[j], dm);
    float sc[5][5];
    #pragma unroll
    for (int b = 0; b < 5; b++)
        #pragma unroll
        for (int a = 0; a < 5; a++) sc[b][a] = dm[a][b];
    if (u >= TOPK) {
        #pragma unroll
        for (int b = 0; b < 5; b++) {
            float tmp = sc[b][0]; sc[b][0] = sc[b][4]; sc[b][4] = tmp;
            tmp = sc[b][1]; sc[b][1] = sc[b][3]; sc[b][3] = tmp;
        }
    }
    g_nwr[j*2*TOPK + u] = nw5(sc);
}

__global__ void match_kernel() {
    int gi = blockIdx.x * blockDim.x + threadIdx.x;
    if (gi >= 2*N_LINES) return;
    int rev = gi >= N_LINES;
    int i = rev ? (gi - N_LINES) : gi;
    const float* nw = rev ? g_nwr : g_nwf;
    const int* topk = rev ? g_topkr : g_topkf;
    float best = nw[i*2*TOPK];
    int bt = 0;
    #pragma unroll
    for (int t = 1; t < 2*TOPK; t++) {
        float v = nw[i*2*TOPK + t];
        if (v > best) { best = v; bt = t; }
    }
    int m = topk[i*TOPK + (bt % TOPK)];
    if (rev) g_mr[i] = m; else g_mf[i] = m;
}

__global__ void finalize_kernel(void* out, int out_size) {
    int idx = blockIdx.x * blockDim.x + threadIdx.x;
    if (out_size >= N_LINES + N_LINES*2*TOPK) {
        float* o = (float*)out;
        if (idx < N_LINES) {
            int mf = g_mf[idx];
            o[idx] = (g_mr[mf] == idx) ? (float)mf : -1.0f;
        } else if (idx < N_LINES + N_LINES*2*TOPK) {
            o[idx] = g_nwf[idx - N_LINES];
        }
    } else if (out_size == N_LINES) {
        if (idx < N_LINES) {
            int mf = g_mf[idx];
            ((int*)out)[idx] = (g_mr[mf] == idx) ? mf : -1;
        }
    } else if (out_size == N_LINES*2*TOPK) {
        if (idx < N_LINES*2*TOPK) ((float*)out)[idx] = g_nwf[idx];
    }
}

// ---------------- launch ----------------
extern "C" void kernel_launch(void* const* d_in, const int* in_sizes, int n_in,
                              void* d_out, int out_size) {
    const float* seg1  = (const float*)d_in[0];
    const float* seg2  = (const float*)d_in[1];
    const float* desc1 = (const float*)d_in[2];
    const float* desc2 = (const float*)d_in[3];

    int tr_blocks = (HH*WW*DIM + 255) / 256;
    transpose_desc<<<tr_blocks, 256>>>(desc1, 0);
    transpose_desc<<<tr_blocks, 256>>>(desc2, 1);

    sample_kernel<<<NPTS, DIM>>>(seg1, 0);
    sample_kernel<<<NPTS, DIM>>>(seg2, 1);

    dim3 gs(N_LINES/BT, N_LINES/BT);
    linescore_kernel<<<gs, 256>>>();

    dim3 cg(N_LINES, 2);
    cand_kernel<<<cg, 256>>>();
    refine_kernel<<<cg, 128>>>();

    int nw_total = N_LINES*2*TOPK;
    nw_fwd_kernel<<<(nw_total + 127)/128, 128>>>();
    nw_rev_kernel<<<(nw_total + 127)/128, 128>>>();

    match_kernel<<<(2*N_LINES + 127)/128, 128>>>();

    int out_threads = N_LINES + N_LINES*2*TOPK;
    finalize_kernel<<<(out_threads + 255)/256, 256>>>(d_out, out_size);
}

// round 10
// speedup vs baseline: 2.3419x; 1.6342x over previous
#include <cuda_runtime.h>
#include <math.h>
#include <stdint.h>

#define N_LINES 1200
#define SAMP 5
#define NPTS (N_LINES*SAMP)     // 6000
#define DIM 128
#define HH 128
#define WW 128
#define TOPK 10
#define CAND 16
#define GAPC 0.1f
#define BT 16                    // lines per block edge
#define KC 32                    // K chunk
#define ROWS 80                  // BT*SAMP
#define PITCH 36                 // words per smem row (32 + 4 pad, 16B-aligned)

// ---------------- device scratch ----------------
__device__ float g_desc1t[HH*WW*DIM];   // [y][x][d]
__device__ float g_desc2t[HH*WW*DIM];
__device__ float g_d1[NPTS*DIM];        // sampled normalized descriptors [pt][d]
__device__ float g_d2[NPTS*DIM];
__device__ int   g_ns1[N_LINES];
__device__ int   g_ns2[N_LINES];
__device__ float g_ls [N_LINES*N_LINES];
__device__ float g_lsT[N_LINES*N_LINES];
__device__ int   g_candf[N_LINES*CAND];
__device__ int   g_candr[N_LINES*CAND];
__device__ int   g_topkf[N_LINES*TOPK];
__device__ int   g_topkr[N_LINES*TOPK];
__device__ float g_nwf[N_LINES*2*TOPK];
__device__ float g_nwr[N_LINES*2*TOPK];
__device__ int   g_mf[N_LINES];
__device__ int   g_mr[N_LINES];

__device__ __forceinline__ uint32_t smem_u32(const void* p) {
    uint32_t a;
    asm("{ .reg .u64 t; cvta.to.shared.u64 t, %1; cvt.u32.u64 %0, t; }" : "=r"(a) : "l"(p));
    return a;
}
#define CP_ASYNC16(dst, src) \
    asm volatile("cp.async.cg.shared.global [%0], [%1], 16;" :: "r"(dst), "l"(src) : "memory")
#define CP_COMMIT() asm volatile("cp.async.commit_group;" ::: "memory")
#define CP_WAIT0()  asm volatile("cp.async.wait_group 0;" ::: "memory")
#define CP_WAIT1()  asm volatile("cp.async.wait_group 1;" ::: "memory")

// ---------------- transpose desc [d][y][x] -> [y][x][d] (both images) ----------------
__global__ void transpose_desc(const float* __restrict__ in1, const float* __restrict__ in2) {
    int idx = blockIdx.x * blockDim.x + threadIdx.x;
    int which = idx >= HH*WW*DIM;
    int i = which ? idx - HH*WW*DIM : idx;
    const float* in = which ? in2 : in1;
    int d = i % DIM;
    int x = (i / DIM) % WW;
    int y = i / (DIM*WW);
    float v = in[d*(HH*WW) + y*WW + x];
    if (which == 0) g_desc1t[i] = v; else g_desc2t[i] = v;
}

// ---------------- sample points + bilinear descriptors + normalize ----------------
__global__ void sample_kernel(const float* __restrict__ seg, int which) {
    int pid  = blockIdx.x;            // 0..NPTS-1
    int line = pid / SAMP;
    int k    = pid % SAMP;
    int d    = threadIdx.x;           // 0..127

    float s0 = seg[line*4+0], s1 = seg[line*4+1];
    float e0 = seg[line*4+2], e1 = seg[line*4+3];
    float dy = __fsub_rn(e0, s0), dx = __fsub_rn(e1, s1);
    float len = __fsqrt_rn(__fadd_rn(__fmul_rn(dy,dy), __fmul_rn(dx,dx)));
    float nsf = floorf(__fmul_rn(len, 0.125f));
    nsf = fminf(fmaxf(nsf, 2.0f), 5.0f);
    float inv = __fsub_rn(nsf, 1.0f);
    float i0 = __fdiv_rn(dy, inv);
    float i1 = __fdiv_rn(dx, inv);
    float kf = (float)k;
    bool valid = kf < nsf;
    float p0 = valid ? __fadd_rn(s0, __fmul_rn(kf, i0)) : 0.0f;
    float p1 = valid ? __fadd_rn(s1, __fmul_rn(kf, i1)) : 0.0f;

    float xn = __fsub_rn(__fdiv_rn(__fmul_rn(2.0f, p1), 511.0f), 1.0f);
    float yn = __fsub_rn(__fdiv_rn(__fmul_rn(2.0f, p0), 511.0f), 1.0f);
    float ix = __fmul_rn(__fsub_rn(__fmul_rn(__fadd_rn(xn,1.0f),(float)WW),1.0f), 0.5f);
    float iy = __fmul_rn(__fsub_rn(__fmul_rn(__fadd_rn(yn,1.0f),(float)HH),1.0f), 0.5f);
    float x0f = floorf(ix), y0f = floorf(iy);
    float wx = __fsub_rn(ix, x0f), wy = __fsub_rn(iy, y0f);
    int x0 = (int)x0f, y0 = (int)y0f;

    const float* img = (which == 0) ? g_desc1t : g_desc2t;
    auto G = [&](int xi, int yi) -> float {
        bool inb = (xi >= 0) && (xi < WW) && (yi >= 0) && (yi < HH);
        int xc = min(max(xi, 0), WW-1);
        int yc = min(max(yi, 0), HH-1);
        float v = img[(yc*WW + xc)*DIM + d];
        return inb ? v : 0.0f;
    };
    float w00 = __fmul_rn(__fsub_rn(1.0f,wx), __fsub_rn(1.0f,wy));
    float w10 = __fmul_rn(wx, __fsub_rn(1.0f,wy));
    float w01 = __fmul_rn(__fsub_rn(1.0f,wx), wy);
    float w11 = __fmul_rn(wx, wy);
    float v = __fadd_rn(__fadd_rn(__fadd_rn(
                __fmul_rn(G(x0,y0),w00), __fmul_rn(G(x0+1,y0),w10)),
                __fmul_rn(G(x0,y0+1),w01)), __fmul_rn(G(x0+1,y0+1),w11));

    float t = __fmul_rn(v,v);
    #pragma unroll
    for (int o = 16; o; o >>= 1) t = __fadd_rn(t, __shfl_xor_sync(0xffffffffu, t, o));
    __shared__ float red[4];
    __shared__ float tot;
    if ((threadIdx.x & 31) == 0) red[threadIdx.x >> 5] = t;
    __syncthreads();
    if (threadIdx.x == 0)
        tot = __fsqrt_rn(__fadd_rn(__fadd_rn(red[0],red[1]),__fadd_rn(red[2],red[3])));
    __syncthreads();

    float* dout = (which == 0) ? g_d1 : g_d2;
    dout[pid*DIM + d] = __fdiv_rn(v, tot);

    if (d == 0 && k == 0) {
        if (which == 0) g_ns1[line] = (int)nsf; else g_ns2[line] = (int)nsf;
    }
}

// ---------------- fused GEMM + line-score reduction (cp.async double-buffered) ----------------
__global__ __launch_bounds__(256) void linescore_kernel() {
    __shared__ __align__(16) float As[2][ROWS][PITCH];
    __shared__ __align__(16) float Bs[2][ROWS][PITCH];
    int tid = threadIdx.x;
    int ti = tid >> 4;        // 0..15
    int tj = tid & 15;        // 0..15
    int ib = blockIdx.y * BT;
    int jb = blockIdx.x * BT;

    const float* Ag = g_d1 + (ib*SAMP)*DIM;
    const float* Bg = g_d2 + (jb*SAMP)*DIM;
    uint32_t sbA = smem_u32(&As[0][0][0]);
    uint32_t sbB = smem_u32(&Bs[0][0][0]);

    // async-load one K-chunk into a slot: 80 rows x 32 floats each matrix
    auto load_chunk = [&](int slot, int k0) {
        #pragma unroll
        for (int i = 0; i < 5; i++) {
            int idx = tid + i*256;          // 0..1279
            int isB = idx >= 640;
            int r   = (idx - (isB ? 640 : 0)) >> 3;
            int cs  = idx & 7;              // 16B segment within 32 floats
            uint32_t dst = (isB ? sbB : sbA)
                + (uint32_t)((slot*ROWS + r)*PITCH + cs*4) * 4u;
            const float* src = (isB ? Bg : Ag) + r*DIM + k0 + cs*4;
            CP_ASYNC16(dst, src);
        }
        CP_COMMIT();
    };

    float acc[5][5];
    #pragma unroll
    for (int s = 0; s < 5; s++)
        #pragma unroll
        for (int u = 0; u < 5; u++) acc[s][u] = 0.0f;

    load_chunk(0, 0);
    #pragma unroll
    for (int c = 0; c < 4; c++) {
        if (c < 3) { load_chunk((c+1)&1, (c+1)*KC); CP_WAIT1(); }
        else       { CP_WAIT0(); }
        __syncthreads();
        int sl = c & 1;
        #pragma unroll
        for (int k = 0; k < KC; k++) {
            float a[5], b[5];
            #pragma unroll
            for (int s = 0; s < 5; s++) a[s] = As[sl][ti*5+s][k];
            #pragma unroll
            for (int u = 0; u < 5; u++) b[u] = Bs[sl][tj*5+u][k];
            #pragma unroll
            for (int s = 0; s < 5; s++)
                #pragma unroll
                for (int u = 0; u < 5; u++) acc[s][u] += a[s]*b[u];
        }
        __syncthreads();
    }

    int i = ib + ti, j = jb + tj;
    int na = g_ns1[i], nb = g_ns2[j];

    float sc[5][5];
    #pragma unroll
    for (int s = 0; s < 5; s++)
        #pragma unroll
        for (int u = 0; u < 5; u++)
            sc[s][u] = (s < na && u < nb) ? acc[s][u] : -1.0f;

    float sum1 = 0.0f, c1 = 0.0f;
    #pragma unroll
    for (int s = 0; s < 5; s++) {
        float m = sc[s][0];
        #pragma unroll
        for (int u = 1; u < 5; u++) m = fmaxf(m, sc[s][u]);
        if (m != -1.0f) { sum1 += m; c1 += 1.0f; }
    }
    float sum2 = 0.0f, c2 = 0.0f;
    #pragma unroll
    for (int u = 0; u < 5; u++) {
        float m = sc[0][u];
        #pragma unroll
        for (int s = 1; s < 5; s++) m = fmaxf(m, sc[s][u]);
        if (m != -1.0f) { sum2 += m; c2 += 1.0f; }
    }
    float ls = (sum1/c1 + sum2/c2) * 0.5f;
    g_ls [i*N_LINES + j] = ls;
    g_lsT[j*N_LINES + i] = ls;
}

// ---------------- top-CAND candidate selection ----------------
__global__ void cand_kernel() {
    int row = blockIdx.x;
    int rev = blockIdx.y;
    int tid = threadIdx.x;
    int lane = tid & 31, warp = tid >> 5;
    __shared__ float vals[N_LINES];
    __shared__ float wv[8];
    __shared__ int   wi[8];

    const float* src = rev ? (g_lsT + row*N_LINES) : (g_ls + row*N_LINES);
    for (int j = tid; j < N_LINES; j += 256) vals[j] = src[j];
    __syncthreads();

    int* cand = rev ? g_candr : g_candf;
    for (int p = 0; p < CAND; p++) {
        float best = -1e30f; int bidx = -1;
        for (int j = tid; j < N_LINES; j += 256) {
            float v = vals[j];
            if (v > best || (v == best && j > bidx)) { best = v; bidx = j; }
        }
        #pragma unroll
        for (int o = 16; o; o >>= 1) {
            float ov = __shfl_xor_sync(0xffffffffu, best, o);
            int   oi = __shfl_xor_sync(0xffffffffu, bidx, o);
            if (ov > best || (ov == best && oi > bidx)) { best = ov; bidx = oi; }
        }
        if (lane == 0) { wv[warp] = best; wi[warp] = bidx; }
        __syncthreads();
        if (warp == 0) {
            best = (lane < 8) ? wv[lane] : -1e30f;
            bidx = (lane < 8) ? wi[lane] : -1;
            #pragma unroll
            for (int o = 4; o; o >>= 1) {
                float ov = __shfl_xor_sync(0xffffffffu, best, o);
                int   oi = __shfl_xor_sync(0xffffffffu, bidx, o);
                if (ov > best || (ov == best && oi > bidx)) { best = ov; bidx = oi; }
            }
            if (lane == 0) {
                cand[row*CAND + p] = bidx;
                vals[bidx] = -1e30f;
            }
        }
        __syncthreads();
    }
}

// ---------------- exact refinement with compensated dots ----------------
__global__ __launch_bounds__(128) void refine_kernel() {
    int r = blockIdx.x;
    int rev = blockIdx.y;
    int tid = threadIdx.x;
    __shared__ float F[5][DIM];
    __shared__ double dm[CAND][5][5];
    __shared__ double scs[CAND];
    __shared__ int cnd[CAND];

    if (tid < CAND) cnd[tid] = rev ? g_candr[r*CAND+tid] : g_candf[r*CAND+tid];
    const float* Ffix = rev ? (g_d2 + r*SAMP*DIM) : (g_d1 + r*SAMP*DIM);
    for (int idx = tid; idx < SAMP*DIM; idx += 128)
        F[idx/DIM][idx%DIM] = Ffix[idx];
    __syncthreads();

    if (tid < CAND*SAMP) {
        int c = tid / SAMP, v = tid % SAMP;
        int j = cnd[c];
        const float* Vg = rev ? (g_d1 + (j*SAMP+v)*DIM) : (g_d2 + (j*SAMP+v)*DIM);
        float s[5], comp[5];
        #pragma unroll
        for (int f = 0; f < 5; f++) { s[f] = 0.0f; comp[f] = 0.0f; }
        for (int k = 0; k < DIM; k++) {
            float b = Vg[k];
            #pragma unroll
            for (int f = 0; f < 5; f++) {
                float a = F[f][k];
                float p  = __fmul_rn(a, b);
                float ep = __fmaf_rn(a, b, -p);
                float t  = __fadd_rn(s[f], p);
                float z  = __fsub_rn(t, s[f]);
                float e  = __fadd_rn(__fsub_rn(s[f], __fsub_rn(t, z)),
                                     __fsub_rn(p, z));
                s[f] = t;
                comp[f] = __fadd_rn(comp[f], __fadd_rn(ep, e));
            }
        }
        #pragma unroll
        for (int f = 0; f < 5; f++) {
            double d = (double)s[f] + (double)comp[f];
            if (!rev) dm[c][f][v] = d;
            else      dm[c][v][f] = d;
        }
    }
    __syncthreads();

    if (tid < CAND) {
        int c = tid; int j = cnd[c];
        int na = rev ? g_ns1[j] : g_ns1[r];
        int nb = rev ? g_ns2[r] : g_ns2[j];
        double sum1 = 0.0, cc1 = 0.0, sum2 = 0.0, cc2 = 0.0;
        for (int a = 0; a < 5; a++) {
            double m = -1.0;
            for (int b = 0; b < 5; b++) {
                double val = (a < na && b < nb) ? dm[c][a][b] : -1.0;
                if (val > m) m = val;
            }
            if (a < na) { sum1 += m; cc1 += 1.0; }
        }
        for (int b = 0; b < 5; b++) {
            double m = -1.0;
            for (int a = 0; a < 5; a++) {
                double val = (a < na && b < nb) ? dm[c][a][b] : -1.0;
                if (val > m) m = val;
            }
            if (b < nb) { sum2 += m; cc2 += 1.0; }
        }
        scs[c] = (sum1/cc1 + sum2/cc2) * 0.5;
    }
    __syncthreads();

    if (tid == 0) {
        bool used[CAND];
        #pragma unroll
        for (int c = 0; c < CAND; c++) used[c] = false;
        int* out = rev ? &g_topkr[r*TOPK] : &g_topkf[r*TOPK];
        for (int p = 0; p < TOPK; p++) {
            double best = -1e300; int bidx = -1, bc = -1;
            for (int c = 0; c < CAND; c++) {
                if (used[c]) continue;
                double v = scs[c]; int idx = cnd[c];
                if (v > best || (v == best && idx > bidx)) { best = v; bidx = idx; bc = c; }
            }
            used[bc] = true;
            out[TOPK-1-p] = bidx;
        }
    }
}

// ---------------- Needleman-Wunsch ----------------
__device__ __forceinline__ float nw5(const float sc[5][5]) {
    float prev[6] = {0,0,0,0,0,0};
    #pragma unroll
    for (int r = 0; r < 5; r++) {
        float nr[6];
        nr[0] = 0.0f;
        float left = 0.0f;
        #pragma unroll
        for (int c = 0; c < 5; c++) {
            float cur = fmaxf(fmaxf(left, prev[c+1]), prev[c] + (sc[r][c] - GAPC));
            nr[c+1] = cur; left = cur;
        }
        #pragma unroll
        for (int c = 0; c < 6; c++) prev[c] = nr[c];
    }
    return prev[5];
}

__device__ __forceinline__ void dot_block(int i, int j, int na, int nb, float dm[5][5]) {
    const float4* pa = (const float4*)(g_d1 + i*SAMP*DIM);
    const float4* pb = (const float4*)(g_d2 + j*SAMP*DIM);
    float acc[5][5];
    #pragma unroll
    for (int a = 0; a < 5; a++)
        #pragma unroll
        for (int b = 0; b < 5; b++) acc[a][b] = 0.0f;
    for (int kk = 0; kk < DIM/4; kk++) {
        float4 x[5], y[5];
        #pragma unroll
        for (int a = 0; a < 5; a++) x[a] = pa[a*(DIM/4) + kk];
        #pragma unroll
        for (int b = 0; b < 5; b++) y[b] = pb[b*(DIM/4) + kk];
        #pragma unroll
        for (int a = 0; a < 5; a++)
            #pragma unroll
            for (int b = 0; b < 5; b++)
                acc[a][b] += x[a].x*y[b].x + x[a].y*y[b].y + x[a].z*y[b].z + x[a].w*y[b].w;
    }
    #pragma unroll
    for (int a = 0; a < 5; a++)
        #pragma unroll
        for (int b = 0; b < 5; b++)
            dm[a][b] = (a < na && b < nb) ? acc[a][b] : -1.0f;
}

__global__ void nw_fwd_kernel() {
    int id = blockIdx.x * blockDim.x + threadIdx.x;
    if (id >= N_LINES*2*TOPK) return;
    int i = id / (2*TOPK);
    int t = id % (2*TOPK);
    int j = g_topkf[i*TOPK + (t % TOPK)];
    float dm[5][5];
    dot_block(i, j, g_ns1[i], g_ns2[j], dm);
    if (t >= TOPK) {
        #pragma unroll
        for (int a = 0; a < 5; a++) {
            float tmp = dm[a][0]; dm[a][0] = dm[a][4]; dm[a][4] = tmp;
            tmp = dm[a][1]; dm[a][1] = dm[a][3]; dm[a][3] = tmp;
        }
    }
    g_nwf[id] = nw5(dm);
}

__global__ void nw_rev_kernel() {
    int id = blockIdx.x * blockDim.x + threadIdx.x;
    if (id >= N_LINES*2*TOPK) return;
    int j = id / (2*TOPK);
    int u = id % (2*TOPK);
    int i = g_topkr[j*TOPK + (u % TOPK)];
    float dm[5][5];
    dot_block(i, j, g_ns1[i], g_ns2[j], dm);
    float sc[5][5];
    #pragma unroll
    for (int b = 0; b < 5; b++)
        #pragma unroll
        for (int a = 0; a < 5; a++) sc[b][a] = dm[a][b];
    if (u >= TOPK) {
        #pragma unroll
        for (int b = 0; b < 5; b++) {
            float tmp = sc[b][0]; sc[b][0] = sc[b][4]; sc[b][4] = tmp;
            tmp = sc[b][1]; sc[b][1] = sc[b][3]; sc[b][3] = tmp;
        }
    }
    g_nwr[j*2*TOPK + u] = nw5(sc);
}

__global__ void match_kernel() {
    int gi = blockIdx.x * blockDim.x + threadIdx.x;
    if (gi >= 2*N_LINES) return;
    int rev = gi >= N_LINES;
    int i = rev ? (gi - N_LINES) : gi;
    const float* nw = rev ? g_nwr : g_nwf;
    const int* topk = rev ? g_topkr : g_topkf;
    float best = nw[i*2*TOPK];
    int bt = 0;
    #pragma unroll
    for (int t = 1; t < 2*TOPK; t++) {
        float v = nw[i*2*TOPK + t];
        if (v > best) { best = v; bt = t; }
    }
    int m = topk[i*TOPK + (bt % TOPK)];
    if (rev) g_mr[i] = m; else g_mf[i] = m;
}

__global__ void finalize_kernel(void* out, int out_size) {
    int idx = blockIdx.x * blockDim.x + threadIdx.x;
    if (out_size >= N_LINES + N_LINES*2*TOPK) {
        float* o = (float*)out;
        if (idx < N_LINES) {
            int mf = g_mf[idx];
            o[idx] = (g_mr[mf] == idx) ? (float)mf : -1.0f;
        } else if (idx < N_LINES + N_LINES*2*TOPK) {
            o[idx] = g_nwf[idx - N_LINES];
        }
    } else if (out_size == N_LINES) {
        if (idx < N_LINES) {
            int mf = g_mf[idx];
            ((int*)out)[idx] = (g_mr[mf] == idx) ? mf : -1;
        }
    } else if (out_size == N_LINES*2*TOPK) {
        if (idx < N_LINES*2*TOPK) ((float*)out)[idx] = g_nwf[idx];
    }
}

// ---------------- launch ----------------
extern "C" void kernel_launch(void* const* d_in, const int* in_sizes, int n_in,
                              void* d_out, int out_size) {
    const float* seg1  = (const float*)d_in[0];
    const float* seg2  = (const float*)d_in[1];
    const float* desc1 = (const float*)d_in[2];
    const float* desc2 = (const float*)d_in[3];

    int tr_blocks = (2*HH*WW*DIM + 255) / 256;
    transpose_desc<<<tr_blocks, 256>>>(desc1, desc2);

    sample_kernel<<<NPTS, DIM>>>(seg1, 0);
    sample_kernel<<<NPTS, DIM>>>(seg2, 1);

    dim3 gs(N_LINES/BT, N_LINES/BT);
    linescore_kernel<<<gs, 256>>>();

    dim3 cg(N_LINES, 2);
    cand_kernel<<<cg, 256>>>();
    refine_kernel<<<cg, 128>>>();

    int nw_total = N_LINES*2*TOPK;
    nw_fwd_kernel<<<(nw_total + 127)/128, 128>>>();
    nw_rev_kernel<<<(nw_total + 127)/128, 128>>>();

    match_kernel<<<(2*N_LINES + 127)/128, 128>>>();

    int out_threads = N_LINES + N_LINES*2*TOPK;
    finalize_kernel<<<(out_threads + 255)/256, 256>>>(d_out, out_size);
}